// round 16
// baseline (speedup 1.0000x reference)
#include <cuda_runtime.h>
#include <cuda_bf16.h>
#include <cstdint>

// DynamicMaskHead: 128 instances, MLP 10 -> 8 -> 8 -> 1 over 160x160 px (fp32).
// Persistent single-wave kernel: 592 CTAs (4/SM), 8 px/thread (tile=1024 px),
// direct streaming LDG.128 (no smem ring). Halves weight-LDS wavefronts per
// pixel vs the 4-px version while keeping 16 warps/SM for latency cover.
// Weights (<=2 instances per CTA run) preloaded once, duplicated float2
// halves so one LDS.64 broadcast feeds fma.rn.f32x2 directly.

#define NINST 128
#define CIN   10
#define CMID  8
#define HW    25600
#define HW4   (HW / 4)
#define TPB   128
#define TILE4 256                       // float4 per tile (1024 px)
#define TILES_PER_INST 25
#define NCTA 592                        // 4 per SM, one wave

__device__ __forceinline__ float2 ffma2(float2 a, float2 b, float2 c) {
    float2 d;
    asm("fma.rn.f32x2 %0, %1, %2, %3;"
        : "=l"(reinterpret_cast<unsigned long long&>(d))
        : "l"(reinterpret_cast<unsigned long long&>(a)),
          "l"(reinterpret_cast<unsigned long long&>(b)),
          "l"(reinterpret_cast<unsigned long long&>(c)));
    return d;
}

__device__ __forceinline__ float2 relu2(float2 a) {
    return make_float2(fmaxf(a.x, 0.0f), fmaxf(a.y, 0.0f));
}

__global__ void __launch_bounds__(TPB, 4)
mask_head_kernel(const float* __restrict__ feat,
                 const float* __restrict__ params,
                 float* __restrict__ out) {
    // Double-buffered weight sets (a CTA's run spans <= 2 instances).
    __shared__ float2 w0s[2][CMID * CIN];
    __shared__ float2 w1s[2][CMID * CMID];
    __shared__ float2 w2s[2][CMID];
    __shared__ float2 b0s[2][CMID];
    __shared__ float2 b1s[2][CMID];
    __shared__ float2 b2s[2];

    const int tid = threadIdx.x;
    const int b   = blockIdx.x;

    // 3200 tiles over 592 CTAs: first 240 get 6, remaining 352 get 5.
    int first, count;
    if (b < 240) { first = b * 6;                count = 6; }
    else         { first = 1440 + (b - 240) * 5; count = 5; }

    const int inst0 = first / TILES_PER_INST;
    const int inst1 = (first + count - 1) / TILES_PER_INST;  // inst0 or inst0+1

    const float4* fin4 = reinterpret_cast<const float4*>(feat);
    float4* out4 = reinterpret_cast<float4*>(out);

    // Preload both weight sets.
    for (int i = tid; i < 169; i += TPB) {
        float va = params[inst0 * 169 + i];
        float vb = params[inst1 * 169 + i];
        float2 a2  = make_float2(va, va);
        float2 b2v = make_float2(vb, vb);
        if      (i < 80)  { w0s[0][i]       = a2; w0s[1][i]       = b2v; }
        else if (i < 144) { w1s[0][i - 80]  = a2; w1s[1][i - 80]  = b2v; }
        else if (i < 152) { w2s[0][i - 144] = a2; w2s[1][i - 144] = b2v; }
        else if (i < 160) { b0s[0][i - 152] = a2; b0s[1][i - 152] = b2v; }
        else if (i < 168) { b1s[0][i - 160] = a2; b1s[1][i - 160] = b2v; }
        else              { b2s[0]          = a2; b2s[1]          = b2v; }
    }
    __syncthreads();   // only block barrier in the kernel

    for (int i = 0; i < count; i++) {
        const int item = first + i;
        const int inst = item / TILES_PER_INST;
        const int tile = item % TILES_PER_INST;
        const int wsel = (inst != inst0) ? 1 : 0;

        // Thread owns float4 slots tid and tid+128 of each channel chunk.
        const float4* g = fin4 + inst * CIN * HW4 + tile * TILE4 + tid;
        const float2* w0p = w0s[wsel];
        const float2* w1p = w1s[wsel];
        const float2* w2p = w2s[wsel];
        const float2* b0p = b0s[wsel];
        const float2* b1p = b1s[wsel];

        // ---- Layer 0 (10 -> 8, ReLU), 8 px = 4 f32x2 lanes ----
        float2 h0[CMID][4];
#pragma unroll
        for (int o = 0; o < CMID; o++) {
            float2 bb = b0p[o];
#pragma unroll
            for (int j = 0; j < 4; j++) h0[o][j] = bb;
        }

#pragma unroll
        for (int k = 0; k < CIN; k++) {
            float4 v0 = g[k * HW4];
            float4 v1 = g[k * HW4 + 128];
            float2 x[4] = { make_float2(v0.x, v0.y), make_float2(v0.z, v0.w),
                            make_float2(v1.x, v1.y), make_float2(v1.z, v1.w) };
#pragma unroll
            for (int o = 0; o < CMID; o++) {
                float2 w = w0p[o * CIN + k];
#pragma unroll
                for (int j = 0; j < 4; j++) h0[o][j] = ffma2(w, x[j], h0[o][j]);
            }
        }
#pragma unroll
        for (int o = 0; o < CMID; o++)
#pragma unroll
            for (int j = 0; j < 4; j++) h0[o][j] = relu2(h0[o][j]);

        // ---- Layers 1+2 fused ----
        float2 acc[4];
        {
            float2 bb = b2s[wsel];
#pragma unroll
            for (int j = 0; j < 4; j++) acc[j] = bb;
        }
#pragma unroll
        for (int o = 0; o < CMID; o++) {
            float2 t[4];
            float2 bb = b1p[o];
#pragma unroll
            for (int j = 0; j < 4; j++) t[j] = bb;
#pragma unroll
            for (int k = 0; k < CMID; k++) {
                float2 w = w1p[o * CMID + k];
#pragma unroll
                for (int j = 0; j < 4; j++) t[j] = ffma2(w, h0[k][j], t[j]);
            }
            float2 w2 = w2p[o];
#pragma unroll
            for (int j = 0; j < 4; j++) acc[j] = ffma2(w2, relu2(t[j]), acc[j]);
        }

        float4* ob = out4 + inst * HW4 + tile * TILE4 + tid;
        ob[0]   = make_float4(acc[0].x, acc[0].y, acc[1].x, acc[1].y);
        ob[128] = make_float4(acc[2].x, acc[2].y, acc[3].x, acc[3].y);
    }
}

extern "C" void kernel_launch(void* const* d_in, const int* in_sizes, int n_in,
                              void* d_out, int out_size) {
    const float* feat   = (const float*)d_in[0];
    const float* params = (const float*)d_in[1];
    float* out          = (float*)d_out;

    mask_head_kernel<<<NCTA, TPB>>>(feat, params, out);
}